// round 2
// baseline (speedup 1.0000x reference)
#include <cuda_runtime.h>

// Problem constants
#define NN      50000       // nodes
#define NE      800000      // edges
#define D       128         // d_in = d_msg = d_up
#define DH      512         // hidden
#define K1      256         // 2*D (concat input width)
#define TM      128         // tile rows (edges or nodes)
#define TN      128         // tile cols = chunk of DH
#define KB      32          // K-step
#define NCHUNK  (DH/TN)     // 4
#define THREADS 256
#define HS      132         // padded stride for h tile in smem
#define BS      132         // padded stride for B tile in smem

// Scratch: aggregated messages per node
__device__ float g_agg[NN * D];

// smem layout (floats):
//   sA : TM*K1      = 32768   (gathered A tile, row-major stride K1)
//   sH : TM*HS      = 16896   (relu(h_chunk), stride HS)
//   sB : KB*BS      = 4224    (weight K-slab, stride BS)
//   idx: 2*TM ints
#define SMEM_FLOATS (TM*K1 + TM*HS + KB*BS)
#define SMEM_BYTES  (SMEM_FLOATS*4 + 2*TM*4)

__global__ void zero_agg_kernel() {
    float4 z = make_float4(0.f, 0.f, 0.f, 0.f);
    int total = NN * D / 4;
    for (int p = blockIdx.x * blockDim.x + threadIdx.x; p < total;
         p += gridDim.x * blockDim.x)
        ((float4*)g_agg)[p] = z;
}

__device__ __forceinline__ int clamp_idx(int v) {
    v = v < 0 ? 0 : v;
    return v >= NN ? NN - 1 : v;
}

// 8x8 micro-tile FMA over a KB-slab.
template <int LDA>
__device__ __forceinline__ void mm_tile(const float* __restrict__ Ablk,
                                        const float* __restrict__ Bblk,
                                        int tx, float acc[8][8]) {
#pragma unroll 8
    for (int k = 0; k < KB; ++k) {
        float a[8];
#pragma unroll
        for (int i = 0; i < 8; ++i) a[i] = Ablk[i * LDA + k];
        const float4 bl = *(const float4*)(Bblk + k * BS + tx * 8);
        const float4 bh = *(const float4*)(Bblk + k * BS + tx * 8 + 4);
        const float b[8] = {bl.x, bl.y, bl.z, bl.w, bh.x, bh.y, bh.z, bh.w};
#pragma unroll
        for (int i = 0; i < 8; ++i)
#pragma unroll
            for (int j = 0; j < 8; ++j)
                acc[i][j] = fmaf(a[i], b[j], acc[i][j]);
    }
}

// Fused 2-layer MLP tile kernel.
// IS_EDGE=true : A = [x[tgt] | x[src]] per edge; epilogue = atomic scatter into g_agg.
// IS_EDGE=false: A = [x[n]   | agg[n]] per node; epilogue = store to out.
template <bool IS_EDGE>
__global__ __launch_bounds__(THREADS, 1)
void mpnn_mlp_kernel(const float* __restrict__ x,
                     const int* __restrict__ edge_index,
                     const float* __restrict__ W1, const float* __restrict__ b1,
                     const float* __restrict__ W2, const float* __restrict__ b2,
                     float* __restrict__ outp) {
    extern __shared__ float smem[];
    float* sA = smem;                    // [TM][K1]
    float* sH = sA + TM * K1;            // [TM][HS]
    float* sB = sH + TM * HS;            // [KB][BS]
    int* sTgt = (int*)(sB + KB * BS);    // [TM]
    int* sSrc = sTgt + TM;               // [TM]

    const int tid = threadIdx.x;
    const int ty = tid >> 4;   // 0..15 -> rows ty*8..+8
    const int tx = tid & 15;   // 0..15 -> cols tx*8..+8
    const int rowBase = blockIdx.x * TM;

    if (IS_EDGE) {
        if (tid < TM) {
            int e = rowBase + tid;
            sSrc[tid] = clamp_idx(edge_index[e]);        // row 0: source j
            sTgt[tid] = clamp_idx(edge_index[NE + e]);   // row 1: target i
        }
        __syncthreads();
    }

    // ---- Stage A tile: [TM][K1] = concat halves, gathered. 32 float4/thread.
    const float4* x4 = (const float4*)x;
    const float4* agg4 = (const float4*)g_agg;
#pragma unroll
    for (int p = 0; p < (TM * K1 / 4) / THREADS; ++p) {   // 32
        int f = p * THREADS + tid;
        int r = f >> 6;        // 64 float4 per row
        int q = f & 63;        // float4 index within row
        float4 v;
        if (IS_EDGE) {
            if (q < 32) v = x4[(size_t)sTgt[r] * 32 + q];          // x_i (target)
            else        v = x4[(size_t)sSrc[r] * 32 + (q - 32)];   // x_j (source)
        } else {
            int n = rowBase + r;
            if (n >= NN) n = 0;
            if (q < 32) v = x4[(size_t)n * 32 + q];
            else        v = agg4[(size_t)n * 32 + (q - 32)];
        }
        ((float4*)sA)[f] = v;
    }

    // ---- Output accumulator (msg or out), init with b2 (per row/edge!)
    float accO[8][8];
#pragma unroll
    for (int j = 0; j < 8; ++j) {
        float bv = b2[tx * 8 + j];
#pragma unroll
        for (int i = 0; i < 8; ++i) accO[i][j] = bv;
    }

    for (int ch = 0; ch < NCHUNK; ++ch) {
        // ---- GEMM1: accH = A @ W1[:, ch*TN..+TN] + b1
        float accH[8][8];
#pragma unroll
        for (int j = 0; j < 8; ++j) {
            float bv = b1[ch * TN + tx * 8 + j];
#pragma unroll
            for (int i = 0; i < 8; ++i) accH[i][j] = bv;
        }
        for (int kb = 0; kb < K1 / KB; ++kb) {
            __syncthreads();
#pragma unroll
            for (int p = 0; p < (KB * TN / 4) / THREADS; ++p) {   // 4
                int f = p * THREADS + tid;
                int k = f >> 5;          // 32 float4 per row
                int c4 = f & 31;
                float4 v = *(const float4*)&W1[(size_t)(kb * KB + k) * DH + ch * TN + c4 * 4];
                *(float4*)&sB[k * BS + c4 * 4] = v;
            }
            __syncthreads();
            mm_tile<K1>(&sA[(ty * 8) * K1 + kb * KB], sB, tx, accH);
        }
        __syncthreads();

        // ---- relu(h) -> smem
#pragma unroll
        for (int i = 0; i < 8; ++i) {
            float4 v0, v1;
            v0.x = fmaxf(accH[i][0], 0.f); v0.y = fmaxf(accH[i][1], 0.f);
            v0.z = fmaxf(accH[i][2], 0.f); v0.w = fmaxf(accH[i][3], 0.f);
            v1.x = fmaxf(accH[i][4], 0.f); v1.y = fmaxf(accH[i][5], 0.f);
            v1.z = fmaxf(accH[i][6], 0.f); v1.w = fmaxf(accH[i][7], 0.f);
            *(float4*)&sH[(ty * 8 + i) * HS + tx * 8] = v0;
            *(float4*)&sH[(ty * 8 + i) * HS + tx * 8 + 4] = v1;
        }

        // ---- GEMM2: accO += relu(h) @ W2[ch*TN..+TN, :]
        for (int kb = 0; kb < TN / KB; ++kb) {
            __syncthreads();
#pragma unroll
            for (int p = 0; p < (KB * D / 4) / THREADS; ++p) {    // 4
                int f = p * THREADS + tid;
                int k = f >> 5;
                int c4 = f & 31;
                float4 v = *(const float4*)&W2[(size_t)(ch * TN + kb * KB + k) * D + c4 * 4];
                *(float4*)&sB[k * BS + c4 * 4] = v;
            }
            __syncthreads();
            mm_tile<HS>(&sH[(ty * 8) * HS + kb * KB], sB, tx, accO);
        }
    }

    // ---- Epilogue
    if (IS_EDGE) {
#pragma unroll
        for (int i = 0; i < 8; ++i) {
            int r = ty * 8 + i;
            float* dst = g_agg + (size_t)sTgt[r] * D + tx * 8;
            asm volatile("red.global.add.v4.f32 [%0], {%1,%2,%3,%4};" ::
                "l"(dst), "f"(accO[i][0]), "f"(accO[i][1]),
                "f"(accO[i][2]), "f"(accO[i][3]) : "memory");
            asm volatile("red.global.add.v4.f32 [%0], {%1,%2,%3,%4};" ::
                "l"(dst + 4), "f"(accO[i][4]), "f"(accO[i][5]),
                "f"(accO[i][6]), "f"(accO[i][7]) : "memory");
        }
    } else {
#pragma unroll
        for (int i = 0; i < 8; ++i) {
            int n = rowBase + ty * 8 + i;
            if (n < NN) {
                float4 v0 = make_float4(accO[i][0], accO[i][1], accO[i][2], accO[i][3]);
                float4 v1 = make_float4(accO[i][4], accO[i][5], accO[i][6], accO[i][7]);
                *(float4*)&outp[(size_t)n * D + tx * 8] = v0;
                *(float4*)&outp[(size_t)n * D + tx * 8 + 4] = v1;
            }
        }
    }
}

extern "C" void kernel_launch(void* const* d_in, const int* in_sizes, int n_in,
                              void* d_out, int out_size) {
    const float* x      = (const float*)d_in[0];
    // d_in[1] = degrees (unused by reference)
    const int* ei       = (const int*)d_in[2];   // int32! (JAX x64 disabled)
    const float* W1m = (const float*)d_in[3];
    const float* b1m = (const float*)d_in[4];
    const float* W2m = (const float*)d_in[5];
    const float* b2m = (const float*)d_in[6];
    const float* W1u = (const float*)d_in[7];
    const float* b1u = (const float*)d_in[8];
    const float* W2u = (const float*)d_in[9];
    const float* b2u = (const float*)d_in[10];

    cudaFuncSetAttribute(mpnn_mlp_kernel<true>,
                         cudaFuncAttributeMaxDynamicSharedMemorySize, SMEM_BYTES);
    cudaFuncSetAttribute(mpnn_mlp_kernel<false>,
                         cudaFuncAttributeMaxDynamicSharedMemorySize, SMEM_BYTES);

    zero_agg_kernel<<<256, 256>>>();

    // Edge phase: msg MLP + scatter-add into g_agg
    mpnn_mlp_kernel<true><<<NE / TM, THREADS, SMEM_BYTES>>>(
        x, ei, W1m, b1m, W2m, b2m, nullptr);

    // Node phase: update MLP, direct store
    mpnn_mlp_kernel<false><<<(NN + TM - 1) / TM, THREADS, SMEM_BYTES>>>(
        x, nullptr, W1u, b1u, W2u, b2u, (float*)d_out);
}

// round 4
// speedup vs baseline: 2.7452x; 2.7452x over previous
#include <cuda_runtime.h>
#include <cstdint>

// Problem constants
#define NN      50000       // nodes
#define NE      800000      // edges
#define D       128         // d_in = d_msg = d_up
#define DH      512         // hidden
#define K1      256         // 2*D (concat input width)
#define TM      128         // tile rows (edges or nodes)
#define TN      128         // tile cols = chunk of DH
#define KB      32          // K-slab
#define NCHUNK  (DH/TN)     // 4
#define THREADS 256
#define SA      260         // sA stride (floats): mod 32 == 4 -> conflict-free frags
#define HS      132         // sH stride: mod 32 == 4 -> conflict-free frags
#define BS      136         // sB stride: mod 32 == 8 -> conflict-free frags

// Scratch: aggregated messages per node
__device__ float g_agg[NN * D];

#define SMEM_FLOATS (TM*SA + TM*HS + KB*BS)
#define SMEM_BYTES  (SMEM_FLOATS*4 + 2*TM*4)

__global__ void zero_agg_kernel() {
    float4 z = make_float4(0.f, 0.f, 0.f, 0.f);
    int total = NN * D / 4;
    for (int p = blockIdx.x * blockDim.x + threadIdx.x; p < total;
         p += gridDim.x * blockDim.x)
        ((float4*)g_agg)[p] = z;
}

__device__ __forceinline__ int clamp_idx(int v) {
    v = v < 0 ? 0 : v;
    return v >= NN ? NN - 1 : v;
}

__device__ __forceinline__ float to_tf32(float x) {
    uint32_t u;
    asm("cvt.rna.tf32.f32 %0, %1;" : "=r"(u) : "f"(x));
    return __uint_as_float(u);
}
__device__ __forceinline__ float4 to_tf32_4(float4 v) {
    v.x = to_tf32(v.x); v.y = to_tf32(v.y);
    v.z = to_tf32(v.z); v.w = to_tf32(v.w);
    return v;
}

__device__ __forceinline__ void mma_tf32(float c[4],
                                         uint32_t a0, uint32_t a1, uint32_t a2, uint32_t a3,
                                         uint32_t b0, uint32_t b1) {
    asm volatile(
        "mma.sync.aligned.m16n8k8.row.col.f32.tf32.tf32.f32 "
        "{%0,%1,%2,%3}, {%4,%5,%6,%7}, {%8,%9}, {%0,%1,%2,%3};\n"
        : "+f"(c[0]), "+f"(c[1]), "+f"(c[2]), "+f"(c[3])
        : "r"(a0), "r"(a1), "r"(a2), "r"(a3), "r"(b0), "r"(b1));
}

// One k8 step: 2 m16 stripes x 8 n8 tiles. A from sAh (stride LDA) rows row0..+32,
// B from sB rows ksrow..+8, cols n0..+64.
__device__ __forceinline__ void mma_step(const float* __restrict__ sAh, int LDA, int kcol,
                                         const float* __restrict__ sB, int ksrow,
                                         int row0, int n0, int g, int tig,
                                         float acc[2][8][4]) {
    uint32_t a[2][4];
#pragma unroll
    for (int s = 0; s < 2; ++s) {
        const float* base = sAh + (row0 + s * 16 + g) * LDA + kcol + tig;
        a[s][0] = __float_as_uint(base[0]);
        a[s][1] = __float_as_uint(base[8 * LDA]);
        a[s][2] = __float_as_uint(base[4]);
        a[s][3] = __float_as_uint(base[8 * LDA + 4]);
    }
    uint32_t b[8][2];
#pragma unroll
    for (int nt = 0; nt < 8; ++nt) {
        const float* bb = sB + (ksrow + tig) * BS + n0 + nt * 8 + g;
        b[nt][0] = __float_as_uint(bb[0]);
        b[nt][1] = __float_as_uint(bb[4 * BS]);
    }
#pragma unroll
    for (int s = 0; s < 2; ++s)
#pragma unroll
        for (int nt = 0; nt < 8; ++nt)
            mma_tf32(acc[s][nt], a[s][0], a[s][1], a[s][2], a[s][3],
                     b[nt][0], b[nt][1]);
}

// Fused 2-layer MLP tile kernel (tf32 tensor cores).
// IS_EDGE=true : A = [x[tgt] | x[src]] per edge; epilogue = atomic scatter into g_agg.
// IS_EDGE=false: A = [x[n]   | agg[n]] per node; epilogue = store to out.
template <bool IS_EDGE>
__global__ __launch_bounds__(THREADS, 1)
void mpnn_mlp_kernel(const float* __restrict__ x,
                     const int* __restrict__ edge_index,
                     const float* __restrict__ W1, const float* __restrict__ b1,
                     const float* __restrict__ W2, const float* __restrict__ b2,
                     float* __restrict__ outp) {
    extern __shared__ float smem[];
    float* sA = smem;                    // [TM][SA]
    float* sH = sA + TM * SA;            // [TM][HS]
    float* sB = sH + TM * HS;            // [KB][BS]
    int* sTgt = (int*)(sB + KB * BS);    // [TM]
    int* sSrc = sTgt + TM;               // [TM]

    const int tid = threadIdx.x;
    const int lane = tid & 31;
    const int wid = tid >> 5;
    const int g = lane >> 2;         // groupID (row within m8)
    const int tig = lane & 3;        // thread-in-group (k / col pair idx)
    const int warp_m = wid >> 1;     // 0..3 -> rows warp_m*32..+32
    const int warp_n = wid & 1;      // 0..1 -> cols warp_n*64..+64
    const int row0 = warp_m * 32;
    const int n0 = warp_n * 64;
    const int ty = tid >> 4;         // epilogue mapping
    const int tx = tid & 15;
    const int rowBase = blockIdx.x * TM;

    if (IS_EDGE) {
        if (tid < TM) {
            int e = rowBase + tid;
            sSrc[tid] = clamp_idx(edge_index[e]);        // source j
            sTgt[tid] = clamp_idx(edge_index[NE + e]);   // target i
        }
        __syncthreads();
    }

    // ---- Stage A tile [TM][K1] (tf32-rounded), gathered. 32 float4/thread.
    const float4* x4 = (const float4*)x;
    const float4* agg4 = (const float4*)g_agg;
#pragma unroll
    for (int p = 0; p < (TM * K1 / 4) / THREADS; ++p) {   // 32
        int f = p * THREADS + tid;
        int r = f >> 6;        // 64 float4 per row
        int q = f & 63;
        float4 v;
        if (IS_EDGE) {
            if (q < 32) v = x4[(size_t)sTgt[r] * 32 + q];          // x_i (target)
            else        v = x4[(size_t)sSrc[r] * 32 + (q - 32)];   // x_j (source)
        } else {
            int n = rowBase + r;
            if (n >= NN) n = 0;
            if (q < 32) v = x4[(size_t)n * 32 + q];
            else        v = agg4[(size_t)n * 32 + (q - 32)];
        }
        *(float4*)&sA[r * SA + q * 4] = to_tf32_4(v);
    }

    // ---- Output accumulator, init with b2 per row
    float accO[2][8][4];
#pragma unroll
    for (int nt = 0; nt < 8; ++nt) {
        float2 bv = *(const float2*)&b2[n0 + nt * 8 + tig * 2];
#pragma unroll
        for (int s = 0; s < 2; ++s) {
            accO[s][nt][0] = bv.x; accO[s][nt][1] = bv.y;
            accO[s][nt][2] = bv.x; accO[s][nt][3] = bv.y;
        }
    }

    for (int ch = 0; ch < NCHUNK; ++ch) {
        // ---- GEMM1: accH = A @ W1[:, ch*TN..+TN] + b1
        float accH[2][8][4];
#pragma unroll
        for (int nt = 0; nt < 8; ++nt) {
            float2 bv = *(const float2*)&b1[ch * TN + n0 + nt * 8 + tig * 2];
#pragma unroll
            for (int s = 0; s < 2; ++s) {
                accH[s][nt][0] = bv.x; accH[s][nt][1] = bv.y;
                accH[s][nt][2] = bv.x; accH[s][nt][3] = bv.y;
            }
        }
        for (int kb = 0; kb < K1 / KB; ++kb) {     // 8 slabs
            __syncthreads();
#pragma unroll
            for (int p = 0; p < (KB * TN / 4) / THREADS; ++p) {   // 4
                int f = p * THREADS + tid;
                int k = f >> 5;
                int c4 = f & 31;
                float4 v = *(const float4*)&W1[(size_t)(kb * KB + k) * DH + ch * TN + c4 * 4];
                *(float4*)&sB[k * BS + c4 * 4] = to_tf32_4(v);
            }
            __syncthreads();
#pragma unroll
            for (int ks = 0; ks < 4; ++ks)
                mma_step(sA, SA, kb * KB + ks * 8, sB, ks * 8,
                         row0, n0, g, tig, accH);
        }
        __syncthreads();

        // ---- relu(h), tf32-round -> sH
#pragma unroll
        for (int s = 0; s < 2; ++s)
#pragma unroll
            for (int nt = 0; nt < 8; ++nt) {
                int r = row0 + s * 16 + g;
                int c = n0 + nt * 8 + tig * 2;
                float2 lo, hi;
                lo.x = to_tf32(fmaxf(accH[s][nt][0], 0.f));
                lo.y = to_tf32(fmaxf(accH[s][nt][1], 0.f));
                hi.x = to_tf32(fmaxf(accH[s][nt][2], 0.f));
                hi.y = to_tf32(fmaxf(accH[s][nt][3], 0.f));
                *(float2*)&sH[r * HS + c] = lo;
                *(float2*)&sH[(r + 8) * HS + c] = hi;
            }

        // ---- GEMM2: accO += relu(h) @ W2[ch*TN..+TN, :]
        for (int kb = 0; kb < TN / KB; ++kb) {     // 4 slabs
            __syncthreads();
#pragma unroll
            for (int p = 0; p < (KB * D / 4) / THREADS; ++p) {    // 4
                int f = p * THREADS + tid;
                int k = f >> 5;
                int c4 = f & 31;
                float4 v = *(const float4*)&W2[(size_t)(ch * TN + kb * KB + k) * D + c4 * 4];
                *(float4*)&sB[k * BS + c4 * 4] = to_tf32_4(v);
            }
            __syncthreads();
#pragma unroll
            for (int ks = 0; ks < 4; ++ks)
                mma_step(sH, HS, kb * KB + ks * 8, sB, ks * 8,
                         row0, n0, g, tig, accO);
        }
    }

    // ---- Permute accO through sH for coalesced epilogue
    __syncthreads();
#pragma unroll
    for (int s = 0; s < 2; ++s)
#pragma unroll
        for (int nt = 0; nt < 8; ++nt) {
            int r = row0 + s * 16 + g;
            int c = n0 + nt * 8 + tig * 2;
            *(float2*)&sH[r * HS + c] = make_float2(accO[s][nt][0], accO[s][nt][1]);
            *(float2*)&sH[(r + 8) * HS + c] = make_float2(accO[s][nt][2], accO[s][nt][3]);
        }
    __syncthreads();

    // ---- Epilogue
    if (IS_EDGE) {
#pragma unroll
        for (int i = 0; i < 8; ++i) {
            int r = ty * 8 + i;
            float4 v0 = *(float4*)&sH[r * HS + tx * 8];
            float4 v1 = *(float4*)&sH[r * HS + tx * 8 + 4];
            float* dst = g_agg + (size_t)sTgt[r] * D + tx * 8;
            asm volatile("red.global.add.v4.f32 [%0], {%1,%2,%3,%4};" ::
                "l"(dst), "f"(v0.x), "f"(v0.y), "f"(v0.z), "f"(v0.w) : "memory");
            asm volatile("red.global.add.v4.f32 [%0], {%1,%2,%3,%4};" ::
                "l"(dst + 4), "f"(v1.x), "f"(v1.y), "f"(v1.z), "f"(v1.w) : "memory");
        }
    } else {
#pragma unroll
        for (int i = 0; i < 8; ++i) {
            int r = ty * 8 + i;
            int n = rowBase + r;
            if (n < NN) {
                float4 v0 = *(float4*)&sH[r * HS + tx * 8];
                float4 v1 = *(float4*)&sH[r * HS + tx * 8 + 4];
                *(float4*)&outp[(size_t)n * D + tx * 8] = v0;
                *(float4*)&outp[(size_t)n * D + tx * 8 + 4] = v1;
            }
        }
    }
}

extern "C" void kernel_launch(void* const* d_in, const int* in_sizes, int n_in,
                              void* d_out, int out_size) {
    const float* x      = (const float*)d_in[0];
    // d_in[1] = degrees (unused by reference)
    const int* ei       = (const int*)d_in[2];   // int32 (JAX x64 disabled)
    const float* W1m = (const float*)d_in[3];
    const float* b1m = (const float*)d_in[4];
    const float* W2m = (const float*)d_in[5];
    const float* b2m = (const float*)d_in[6];
    const float* W1u = (const float*)d_in[7];
    const float* b1u = (const float*)d_in[8];
    const float* W2u = (const float*)d_in[9];
    const float* b2u = (const float*)d_in[10];

    cudaFuncSetAttribute(mpnn_mlp_kernel<true>,
                         cudaFuncAttributeMaxDynamicSharedMemorySize, SMEM_BYTES);
    cudaFuncSetAttribute(mpnn_mlp_kernel<false>,
                         cudaFuncAttributeMaxDynamicSharedMemorySize, SMEM_BYTES);

    zero_agg_kernel<<<256, 256>>>();

    // Edge phase: msg MLP + scatter-add into g_agg
    mpnn_mlp_kernel<true><<<NE / TM, THREADS, SMEM_BYTES>>>(
        x, ei, W1m, b1m, W2m, b2m, nullptr);

    // Node phase: update MLP, direct store
    mpnn_mlp_kernel<false><<<(NN + TM - 1) / TM, THREADS, SMEM_BYTES>>>(
        x, nullptr, W1u, b1u, W2u, b2u, (float*)d_out);
}

// round 8
// speedup vs baseline: 4.6093x; 1.6790x over previous
#include <cuda_runtime.h>
#include <cstdint>

// Problem constants
#define NN      50000
#define NE      800000
#define D       128
#define DH      512
#define K1      256       // 2*D
#define TM      128
#define THREADS 256
#define SA      260       // update-kernel A stride (mod 32 == 4)
#define HS      132       // H tile stride (mod 32 == 4)
#define BS      136       // W slab stride (mod 32 == 8)

__device__ float g_agg[NN * D];      // aggregated messages
__device__ float g_P[NN * DH];       // x @ W1m_top + b1m
__device__ float g_Q[NN * DH];       // x @ W1m_bot

#define EDGE_SMEM ((TM*HS + 32*BS) * 4 + 2*TM*4)            // 86016
#define PRE_SMEM  ((TM*HS + 32*BS) * 4)                     // 84992
#define UPD_SMEM  ((TM*SA + TM*HS + 32*BS) * 4 + 2*TM*4)    // 219136

__global__ void zero_agg_kernel() {
    float4 z = make_float4(0.f, 0.f, 0.f, 0.f);
    int total = NN * D / 4;
    for (int p = blockIdx.x * blockDim.x + threadIdx.x; p < total;
         p += gridDim.x * blockDim.x)
        ((float4*)g_agg)[p] = z;
}

__device__ __forceinline__ int clamp_idx(int v) {
    v = v < 0 ? 0 : v;
    return v >= NN ? NN - 1 : v;
}
__device__ __forceinline__ float to_tf32(float x) {
    uint32_t u; asm("cvt.rna.tf32.f32 %0, %1;" : "=r"(u) : "f"(x));
    return __uint_as_float(u);
}
__device__ __forceinline__ float4 to_tf32_4(float4 v) {
    v.x = to_tf32(v.x); v.y = to_tf32(v.y);
    v.z = to_tf32(v.z); v.w = to_tf32(v.w);
    return v;
}

__device__ __forceinline__ void mma_tf32(float c[4],
                                         uint32_t a0, uint32_t a1, uint32_t a2, uint32_t a3,
                                         uint32_t b0, uint32_t b1) {
    asm volatile(
        "mma.sync.aligned.m16n8k8.row.col.f32.tf32.tf32.f32 "
        "{%0,%1,%2,%3}, {%4,%5,%6,%7}, {%8,%9}, {%0,%1,%2,%3};\n"
        : "+f"(c[0]), "+f"(c[1]), "+f"(c[2]), "+f"(c[3])
        : "r"(a0), "r"(a1), "r"(a2), "r"(a3), "r"(b0), "r"(b1));
}

// One k8 step: 2 m16 stripes x 8 n8 tiles (warp tile 32x64).
__device__ __forceinline__ void mma_step(const float* __restrict__ sAh, int LDA, int kcol,
                                         const float* __restrict__ sB, int ksrow,
                                         int row0, int n0, int g, int tig,
                                         float acc[2][8][4]) {
    uint32_t a[2][4];
#pragma unroll
    for (int s = 0; s < 2; ++s) {
        const float* base = sAh + (row0 + s * 16 + g) * LDA + kcol + tig;
        a[s][0] = __float_as_uint(base[0]);
        a[s][1] = __float_as_uint(base[8 * LDA]);
        a[s][2] = __float_as_uint(base[4]);
        a[s][3] = __float_as_uint(base[8 * LDA + 4]);
    }
    uint32_t b[8][2];
#pragma unroll
    for (int nt = 0; nt < 8; ++nt) {
        const float* bb = sB + (ksrow + tig) * BS + n0 + nt * 8 + g;
        b[nt][0] = __float_as_uint(bb[0]);
        b[nt][1] = __float_as_uint(bb[4 * BS]);
    }
#pragma unroll
    for (int s = 0; s < 2; ++s)
#pragma unroll
        for (int nt = 0; nt < 8; ++nt)
            mma_tf32(acc[s][nt], a[s][0], a[s][1], a[s][2], a[s][3],
                     b[nt][0], b[nt][1]);
}

// ============ Precompute: P = x@W1m[0:128] + b1m ; Q = x@W1m[128:256] ============
// grid (ceil(NN/128), 2); blockIdx.y: 0 -> P, 1 -> Q.
__global__ __launch_bounds__(THREADS, 2)
void precompute_kernel(const float* __restrict__ x,
                       const float* __restrict__ W1m,
                       const float* __restrict__ b1m) {
    extern __shared__ float smem[];
    float* sA = smem;                 // [128][HS]  (x tile, K=128)
    float* sB = sA + TM * HS;         // [32][BS]

    const int tid = threadIdx.x;
    const int lane = tid & 31;
    const int wid = tid >> 5;
    const int g = lane >> 2, tig = lane & 3;
    const int row0 = (wid >> 1) * 32, n0 = (wid & 1) * 64;
    const int rowBase = blockIdx.x * TM;
    const int half = blockIdx.y;

    const float4* x4 = (const float4*)x;
#pragma unroll
    for (int p = 0; p < 16; ++p) {
        int f = p * THREADS + tid;
        int r = f >> 5, q = f & 31;
        int n = rowBase + r; if (n >= NN) n = 0;
        *(float4*)&sA[r * HS + q * 4] = to_tf32_4(x4[(size_t)n * 32 + q]);
    }

    float* outArr = half ? g_Q : g_P;
    const float* Wbase = W1m + (size_t)half * 128 * DH;

    for (int ch = 0; ch < 4; ++ch) {
        float acc[2][8][4];
#pragma unroll
        for (int nt = 0; nt < 8; ++nt) {
            float2 bv = half ? make_float2(0.f, 0.f)
                             : *(const float2*)&b1m[ch * 128 + n0 + nt * 8 + tig * 2];
#pragma unroll
            for (int s = 0; s < 2; ++s) {
                acc[s][nt][0] = bv.x; acc[s][nt][1] = bv.y;
                acc[s][nt][2] = bv.x; acc[s][nt][3] = bv.y;
            }
        }
        for (int s = 0; s < 4; ++s) {     // K=128, 4 slabs
            __syncthreads();
#pragma unroll
            for (int p = 0; p < 4; ++p) {
                int f = p * THREADS + tid;
                int k = f >> 5, c4 = f & 31;
                float4 v = *(const float4*)&Wbase[(size_t)(s * 32 + k) * DH + ch * 128 + c4 * 4];
                *(float4*)&sB[k * BS + c4 * 4] = to_tf32_4(v);
            }
            __syncthreads();
#pragma unroll
            for (int ks = 0; ks < 4; ++ks)
                mma_step(sA, HS, s * 32 + ks * 8, sB, ks * 8, row0, n0, g, tig, acc);
        }
        // write acc -> outArr (f32, pre-activation)
#pragma unroll
        for (int s = 0; s < 2; ++s)
#pragma unroll
            for (int nt = 0; nt < 8; ++nt) {
                int r = row0 + s * 16 + g;
                int col = ch * 128 + n0 + nt * 8 + tig * 2;
                int n1 = rowBase + r, n2 = rowBase + r + 8;
                if (n1 < NN)
                    *(float2*)&outArr[(size_t)n1 * DH + col] =
                        make_float2(acc[s][nt][0], acc[s][nt][1]);
                if (n2 < NN)
                    *(float2*)&outArr[(size_t)n2 * DH + col] =
                        make_float2(acc[s][nt][2], acc[s][nt][3]);
            }
    }
}

// ============ Edge kernel: msg = relu(P[i]+Q[j]) @ W2m + b2m ; scatter ============
__global__ __launch_bounds__(THREADS, 2)
void edge_kernel(const int* __restrict__ edge_index,
                 const float* __restrict__ W2m,
                 const float* __restrict__ b2m) {
    extern __shared__ float smem[];
    float* sH = smem;                  // [128][HS]
    float* sB = sH + TM * HS;          // [32][BS]
    int* sTgt = (int*)(sB + 32 * BS);  // [128]
    int* sSrc = sTgt + TM;

    const int tid = threadIdx.x;
    const int lane = tid & 31;
    const int wid = tid >> 5;
    const int g = lane >> 2, tig = lane & 3;
    const int row0 = (wid >> 1) * 32, n0 = (wid & 1) * 64;
    const int ty = tid >> 4, tx = tid & 15;
    const int rowBase = blockIdx.x * TM;

    if (tid < TM) {
        int e = rowBase + tid;
        sSrc[tid] = clamp_idx(edge_index[e]);        // source j
        sTgt[tid] = clamp_idx(edge_index[NE + e]);   // target i
    }

    float accO[2][8][4];
#pragma unroll
    for (int nt = 0; nt < 8; ++nt) {
        float2 bv = *(const float2*)&b2m[n0 + nt * 8 + tig * 2];
#pragma unroll
        for (int s = 0; s < 2; ++s) {
            accO[s][nt][0] = bv.x; accO[s][nt][1] = bv.y;
            accO[s][nt][2] = bv.x; accO[s][nt][3] = bv.y;
        }
    }

    const float4* P4 = (const float4*)g_P;
    const float4* Q4 = (const float4*)g_Q;

    for (int ch = 0; ch < 4; ++ch) {
        __syncthreads();   // prev GEMM done reading sH; idx visible (ch=0)
        // stage sH = relu(P[i] + Q[j]) for this 128-col chunk
#pragma unroll
        for (int p = 0; p < 16; ++p) {
            int f = p * THREADS + tid;
            int r = f >> 5, q = f & 31;
            float4 a = P4[(size_t)sTgt[r] * 128 + ch * 32 + q];
            float4 b = Q4[(size_t)sSrc[r] * 128 + ch * 32 + q];
            float4 v;
            v.x = to_tf32(fmaxf(a.x + b.x, 0.f));
            v.y = to_tf32(fmaxf(a.y + b.y, 0.f));
            v.z = to_tf32(fmaxf(a.z + b.z, 0.f));
            v.w = to_tf32(fmaxf(a.w + b.w, 0.f));
            *(float4*)&sH[r * HS + q * 4] = v;
        }
        for (int s = 0; s < 4; ++s) {   // K-chunk 128, 4 slabs
            __syncthreads();
#pragma unroll
            for (int p = 0; p < 4; ++p) {
                int f = p * THREADS + tid;
                int k = f >> 5, c4 = f & 31;
                float4 v = *(const float4*)&W2m[(size_t)(ch * 128 + s * 32 + k) * D + c4 * 4];
                *(float4*)&sB[k * BS + c4 * 4] = to_tf32_4(v);
            }
            __syncthreads();
#pragma unroll
            for (int ks = 0; ks < 4; ++ks)
                mma_step(sH, HS, s * 32 + ks * 8, sB, ks * 8, row0, n0, g, tig, accO);
        }
    }

    // permute accO through sH, then coalesced scatter
    __syncthreads();
#pragma unroll
    for (int s = 0; s < 2; ++s)
#pragma unroll
        for (int nt = 0; nt < 8; ++nt) {
            int r = row0 + s * 16 + g;
            int c = n0 + nt * 8 + tig * 2;
            *(float2*)&sH[r * HS + c] = make_float2(accO[s][nt][0], accO[s][nt][1]);
            *(float2*)&sH[(r + 8) * HS + c] = make_float2(accO[s][nt][2], accO[s][nt][3]);
        }
    __syncthreads();
#pragma unroll
    for (int i = 0; i < 8; ++i) {
        int r = ty * 8 + i;
        float4 v0 = *(float4*)&sH[r * HS + tx * 8];
        float4 v1 = *(float4*)&sH[r * HS + tx * 8 + 4];
        float* dst = g_agg + (size_t)sTgt[r] * D + tx * 8;
        asm volatile("red.global.add.v4.f32 [%0], {%1,%2,%3,%4};" ::
            "l"(dst), "f"(v0.x), "f"(v0.y), "f"(v0.z), "f"(v0.w) : "memory");
        asm volatile("red.global.add.v4.f32 [%0], {%1,%2,%3,%4};" ::
            "l"(dst + 4), "f"(v1.x), "f"(v1.y), "f"(v1.z), "f"(v1.w) : "memory");
    }
}

// ============ Update kernel (R4 node path): out = relu([x|agg]@W1u+b1u)@W2u+b2u ============
__global__ __launch_bounds__(THREADS, 1)
void update_kernel(const float* __restrict__ x,
                   const float* __restrict__ W1, const float* __restrict__ b1,
                   const float* __restrict__ W2, const float* __restrict__ b2,
                   float* __restrict__ outp) {
    extern __shared__ float smem[];
    float* sA = smem;                 // [128][SA]
    float* sH = sA + TM * SA;         // [128][HS]
    float* sB = sH + TM * HS;         // [32][BS]

    const int tid = threadIdx.x;
    const int lane = tid & 31;
    const int wid = tid >> 5;
    const int g = lane >> 2, tig = lane & 3;
    const int row0 = (wid >> 1) * 32, n0 = (wid & 1) * 64;
    const int ty = tid >> 4, tx = tid & 15;
    const int rowBase = blockIdx.x * TM;

    const float4* x4 = (const float4*)x;
    const float4* agg4 = (const float4*)g_agg;
#pragma unroll
    for (int p = 0; p < 32; ++p) {
        int f = p * THREADS + tid;
        int r = f >> 6, q = f & 63;
        int n = rowBase + r; if (n >= NN) n = 0;
        float4 v = (q < 32) ? x4[(size_t)n * 32 + q] : agg4[(size_t)n * 32 + (q - 32)];
        *(float4*)&sA[r * SA + q * 4] = to_tf32_4(v);
    }

    float accO[2][8][4];
#pragma unroll
    for (int nt = 0; nt < 8; ++nt) {
        float2 bv = *(const float2*)&b2[n0 + nt * 8 + tig * 2];
#pragma unroll
        for (int s = 0; s < 2; ++s) {
            accO[s][nt][0] = bv.x; accO[s][nt][1] = bv.y;
            accO[s][nt][2] = bv.x; accO[s][nt][3] = bv.y;
        }
    }

    for (int ch = 0; ch < 4; ++ch) {
        float accH[2][8][4];
#pragma unroll
        for (int nt = 0; nt < 8; ++nt) {
            float2 bv = *(const float2*)&b1[ch * 128 + n0 + nt * 8 + tig * 2];
#pragma unroll
            for (int s = 0; s < 2; ++s) {
                accH[s][nt][0] = bv.x; accH[s][nt][1] = bv.y;
                accH[s][nt][2] = bv.x; accH[s][nt][3] = bv.y;
            }
        }
        for (int kb = 0; kb < 8; ++kb) {
            __syncthreads();
#pragma unroll
            for (int p = 0; p < 4; ++p) {
                int f = p * THREADS + tid;
                int k = f >> 5, c4 = f & 31;
                float4 v = *(const float4*)&W1[(size_t)(kb * 32 + k) * DH + ch * 128 + c4 * 4];
                *(float4*)&sB[k * BS + c4 * 4] = to_tf32_4(v);
            }
            __syncthreads();
#pragma unroll
            for (int ks = 0; ks < 4; ++ks)
                mma_step(sA, SA, kb * 32 + ks * 8, sB, ks * 8, row0, n0, g, tig, accH);
        }
        __syncthreads();
#pragma unroll
        for (int s = 0; s < 2; ++s)
#pragma unroll
            for (int nt = 0; nt < 8; ++nt) {
                int r = row0 + s * 16 + g;
                int c = n0 + nt * 8 + tig * 2;
                float2 lo, hi;
                lo.x = to_tf32(fmaxf(accH[s][nt][0], 0.f));
                lo.y = to_tf32(fmaxf(accH[s][nt][1], 0.f));
                hi.x = to_tf32(fmaxf(accH[s][nt][2], 0.f));
                hi.y = to_tf32(fmaxf(accH[s][nt][3], 0.f));
                *(float2*)&sH[r * HS + c] = lo;
                *(float2*)&sH[(r + 8) * HS + c] = hi;
            }
        for (int kb = 0; kb < 4; ++kb) {
            __syncthreads();
#pragma unroll
            for (int p = 0; p < 4; ++p) {
                int f = p * THREADS + tid;
                int k = f >> 5, c4 = f & 31;
                float4 v = *(const float4*)&W2[(size_t)(ch * 128 + kb * 32 + k) * D + c4 * 4];
                *(float4*)&sB[k * BS + c4 * 4] = to_tf32_4(v);
            }
            __syncthreads();
#pragma unroll
            for (int ks = 0; ks < 4; ++ks)
                mma_step(sH, HS, kb * 32 + ks * 8, sB, ks * 8, row0, n0, g, tig, accO);
        }
    }

    __syncthreads();
#pragma unroll
    for (int s = 0; s < 2; ++s)
#pragma unroll
        for (int nt = 0; nt < 8; ++nt) {
            int r = row0 + s * 16 + g;
            int c = n0 + nt * 8 + tig * 2;
            *(float2*)&sH[r * HS + c] = make_float2(accO[s][nt][0], accO[s][nt][1]);
            *(float2*)&sH[(r + 8) * HS + c] = make_float2(accO[s][nt][2], accO[s][nt][3]);
        }
    __syncthreads();
#pragma unroll
    for (int i = 0; i < 8; ++i) {
        int r = ty * 8 + i;
        int n = rowBase + r;
        if (n < NN) {
            float4 v0 = *(float4*)&sH[r * HS + tx * 8];
            float4 v1 = *(float4*)&sH[r * HS + tx * 8 + 4];
            *(float4*)&outp[(size_t)n * D + tx * 8] = v0;
            *(float4*)&outp[(size_t)n * D + tx * 8 + 4] = v1;
        }
    }
}

extern "C" void kernel_launch(void* const* d_in, const int* in_sizes, int n_in,
                              void* d_out, int out_size) {
    const float* x   = (const float*)d_in[0];
    const int* ei    = (const int*)d_in[2];   // int32 (JAX x64 disabled)
    const float* W1m = (const float*)d_in[3];
    const float* b1m = (const float*)d_in[4];
    const float* W2m = (const float*)d_in[5];
    const float* b2m = (const float*)d_in[6];
    const float* W1u = (const float*)d_in[7];
    const float* b1u = (const float*)d_in[8];
    const float* W2u = (const float*)d_in[9];
    const float* b2u = (const float*)d_in[10];

    cudaFuncSetAttribute(precompute_kernel,
                         cudaFuncAttributeMaxDynamicSharedMemorySize, PRE_SMEM);
    cudaFuncSetAttribute(edge_kernel,
                         cudaFuncAttributeMaxDynamicSharedMemorySize, EDGE_SMEM);
    cudaFuncSetAttribute(update_kernel,
                         cudaFuncAttributeMaxDynamicSharedMemorySize, UPD_SMEM);

    zero_agg_kernel<<<256, 256>>>();

    dim3 pgrid((NN + TM - 1) / TM, 2);
    precompute_kernel<<<pgrid, THREADS, PRE_SMEM>>>(x, W1m, b1m);

    edge_kernel<<<NE / TM, THREADS, EDGE_SMEM>>>(ei, W2m, b2m);

    update_kernel<<<(NN + TM - 1) / TM, THREADS, UPD_SMEM>>>(
        x, W1u, b1u, W2u, b2u, (float*)d_out);
}

// round 10
// speedup vs baseline: 5.2290x; 1.1344x over previous
#include <cuda_runtime.h>
#include <cuda_fp16.h>
#include <cstdint>

// Problem constants
#define NN      50000
#define NE      800000
#define D       128
#define DH      512
#define TM      128
#define THREADS 256
// half strides (elements): word-stride mod 32 == 4 -> conflict-free frag loads
#define HS2     136      // chunk tiles [128][128+pad] halves
#define SA2     264      // update A tile [128][256+pad] halves
#define BS2     72       // weight slabs [n=128][k=32+pad] halves
#define PS      132      // f32 permute stride

__device__ float g_agg[NN * D];
__device__ float g_P[NN * DH];       // x @ W1m_top + b1m
__device__ float g_Q[NN * DH];       // x @ W1m_bot

// smem byte layouts
#define SZ_H    (TM * HS2 * 2)          // 34816
#define SZ_A2   (TM * SA2 * 2)          // 67584
#define SZ_B    (128 * BS2 * 2)         // 18432
#define SZ_PERM (TM * PS * 4)           // 67584
#define PRE_SMEM  (SZ_H + SZ_B)                       // 53248
#define EDGE_SMEM (SZ_PERM + 2 * TM * 4)              // 68608 (perm overlays sH+sB)
#define UPD_SMEM  (SZ_A2 + SZ_H + SZ_B)               // 120832 (perm overlays sA)

__global__ void zero_agg_kernel() {
    float4 z = make_float4(0.f, 0.f, 0.f, 0.f);
    int total = NN * D / 4;
    for (int p = blockIdx.x * blockDim.x + threadIdx.x; p < total;
         p += gridDim.x * blockDim.x)
        ((float4*)g_agg)[p] = z;
}

__device__ __forceinline__ int clamp_idx(int v) {
    v = v < 0 ? 0 : v;
    return v >= NN ? NN - 1 : v;
}
__device__ __forceinline__ uint2 f4_to_h4(float4 v) {
    half2 lo = __floats2half2_rn(v.x, v.y);
    half2 hi = __floats2half2_rn(v.z, v.w);
    uint2 r;
    r.x = *(uint32_t*)&lo;
    r.y = *(uint32_t*)&hi;
    return r;
}
__device__ __forceinline__ uint32_t f2_to_h2(float a, float b) {
    half2 h = __floats2half2_rn(a, b);
    return *(uint32_t*)&h;
}

__device__ __forceinline__ void mma_f16(float c[4],
                                        uint32_t a0, uint32_t a1, uint32_t a2, uint32_t a3,
                                        uint32_t b0, uint32_t b1) {
    asm volatile(
        "mma.sync.aligned.m16n8k16.row.col.f32.f16.f16.f32 "
        "{%0,%1,%2,%3}, {%4,%5,%6,%7}, {%8,%9}, {%0,%1,%2,%3};\n"
        : "+f"(c[0]), "+f"(c[1]), "+f"(c[2]), "+f"(c[3])
        : "r"(a0), "r"(a1), "r"(a2), "r"(a3), "r"(b0), "r"(b1));
}

// One k16 step: 2 m16 stripes x 8 n8 tiles (warp tile 32x64).
// sA: [row][k] halves, stride LDA. sB: [n][k] halves, stride BS2, 32-k slab at ksrow.
__device__ __forceinline__ void mma_step(const __half* __restrict__ sA, int LDA, int kcol,
                                         const __half* __restrict__ sB, int ksrow,
                                         int row0, int n0, int g, int tig,
                                         float acc[2][8][4]) {
    uint32_t a[2][4];
#pragma unroll
    for (int s = 0; s < 2; ++s) {
        const __half* r0p = sA + (row0 + s * 16 + g) * LDA + kcol + 2 * tig;
        a[s][0] = *(const uint32_t*)r0p;
        a[s][1] = *(const uint32_t*)(r0p + 8 * LDA);
        a[s][2] = *(const uint32_t*)(r0p + 8);
        a[s][3] = *(const uint32_t*)(r0p + 8 * LDA + 8);
    }
    uint32_t b[8][2];
#pragma unroll
    for (int nt = 0; nt < 8; ++nt) {
        const __half* bb = sB + (n0 + nt * 8 + g) * BS2 + ksrow + 2 * tig;
        b[nt][0] = *(const uint32_t*)bb;
        b[nt][1] = *(const uint32_t*)(bb + 8);
    }
#pragma unroll
    for (int s = 0; s < 2; ++s)
#pragma unroll
        for (int nt = 0; nt < 8; ++nt)
            mma_f16(acc[s][nt], a[s][0], a[s][1], a[s][2], a[s][3],
                    b[nt][0], b[nt][1]);
}

// Stage a [n=128][k=32] weight slab (transposed from global [k][n]) as fp16.
// Wg points at global element [k0][n-base]; ldw = global row stride (floats).
__device__ __forceinline__ void stage_wslab(__half* sB, const float* __restrict__ Wg,
                                            int ldw, int tid) {
    const int n_ = tid & 127;
    const int halfk = tid >> 7;
#pragma unroll
    for (int rr = 0; rr < 4; ++rr) {
        int kk = halfk * 16 + rr * 4;
        const float* w = Wg + (size_t)kk * ldw + n_;
        float4 v = make_float4(w[0], w[ldw], w[2 * ldw], w[3 * ldw]);
        *(uint2*)(sB + n_ * BS2 + kk) = f4_to_h4(v);
    }
}

// ============ Precompute: P = x@W1m[0:128] + b1m ; Q = x@W1m[128:256] ============
__global__ __launch_bounds__(THREADS, 2)
void precompute_kernel(const float* __restrict__ x,
                       const float* __restrict__ W1m,
                       const float* __restrict__ b1m) {
    extern __shared__ char smem[];
    __half* sA = (__half*)smem;               // [128][HS2]
    __half* sB = (__half*)(smem + SZ_H);      // [128][BS2]

    const int tid = threadIdx.x;
    const int lane = tid & 31;
    const int wid = tid >> 5;
    const int g = lane >> 2, tig = lane & 3;
    const int row0 = (wid >> 1) * 32, n0 = (wid & 1) * 64;
    const int rowBase = blockIdx.x * TM;
    const int half_sel = blockIdx.y;

    const float4* x4 = (const float4*)x;
#pragma unroll
    for (int p = 0; p < 16; ++p) {
        int f = p * THREADS + tid;
        int r = f >> 5, q = f & 31;
        int n = rowBase + r; if (n >= NN) n = 0;
        *(uint2*)(sA + r * HS2 + q * 4) = f4_to_h4(x4[(size_t)n * 32 + q]);
    }

    float* outArr = half_sel ? g_Q : g_P;
    const float* Wbase = W1m + (size_t)half_sel * 128 * DH;

    for (int ch = 0; ch < 4; ++ch) {
        float acc[2][8][4];
#pragma unroll
        for (int nt = 0; nt < 8; ++nt) {
            float2 bv = half_sel ? make_float2(0.f, 0.f)
                                 : *(const float2*)&b1m[ch * 128 + n0 + nt * 8 + tig * 2];
#pragma unroll
            for (int s = 0; s < 2; ++s) {
                acc[s][nt][0] = bv.x; acc[s][nt][1] = bv.y;
                acc[s][nt][2] = bv.x; acc[s][nt][3] = bv.y;
            }
        }
        for (int s = 0; s < 4; ++s) {     // K=128, 4 slabs of 32
            __syncthreads();
            stage_wslab(sB, Wbase + (size_t)(s * 32) * DH + ch * 128, DH, tid);
            __syncthreads();
#pragma unroll
            for (int ks = 0; ks < 2; ++ks)
                mma_step(sA, HS2, s * 32 + ks * 16, sB, ks * 16, row0, n0, g, tig, acc);
        }
#pragma unroll
        for (int s = 0; s < 2; ++s)
#pragma unroll
            for (int nt = 0; nt < 8; ++nt) {
                int r = row0 + s * 16 + g;
                int col = ch * 128 + n0 + nt * 8 + tig * 2;
                int n1 = rowBase + r, n2 = rowBase + r + 8;
                if (n1 < NN)
                    *(float2*)&outArr[(size_t)n1 * DH + col] =
                        make_float2(acc[s][nt][0], acc[s][nt][1]);
                if (n2 < NN)
                    *(float2*)&outArr[(size_t)n2 * DH + col] =
                        make_float2(acc[s][nt][2], acc[s][nt][3]);
            }
    }
}

// ============ Edge kernel: msg = relu(P[i]+Q[j]) @ W2m + b2m ; scatter ============
__global__ __launch_bounds__(THREADS, 2)
void edge_kernel(const int* __restrict__ edge_index,
                 const float* __restrict__ W2m,
                 const float* __restrict__ b2m) {
    extern __shared__ char smem[];
    __half* sH = (__half*)smem;               // [128][HS2] (pipeline phase)
    __half* sB = (__half*)(smem + SZ_H);      // [128][BS2]
    float* perm = (float*)smem;               // [128][PS]  (epilogue, overlays)
    int* sTgt = (int*)(smem + SZ_PERM);
    int* sSrc = sTgt + TM;

    const int tid = threadIdx.x;
    const int lane = tid & 31;
    const int wid = tid >> 5;
    const int g = lane >> 2, tig = lane & 3;
    const int row0 = (wid >> 1) * 32, n0 = (wid & 1) * 64;
    const int ty = tid >> 4, tx = tid & 15;
    const int rowBase = blockIdx.x * TM;

    if (tid < TM) {
        int e = rowBase + tid;
        sSrc[tid] = clamp_idx(edge_index[e]);        // source j
        sTgt[tid] = clamp_idx(edge_index[NE + e]);   // target i
    }

    float accO[2][8][4];
#pragma unroll
    for (int nt = 0; nt < 8; ++nt) {
        float2 bv = *(const float2*)&b2m[n0 + nt * 8 + tig * 2];
#pragma unroll
        for (int s = 0; s < 2; ++s) {
            accO[s][nt][0] = bv.x; accO[s][nt][1] = bv.y;
            accO[s][nt][2] = bv.x; accO[s][nt][3] = bv.y;
        }
    }

    const float4* P4 = (const float4*)g_P;
    const float4* Q4 = (const float4*)g_Q;

    for (int ch = 0; ch < 4; ++ch) {
        __syncthreads();   // prev GEMM done reading sH; idx visible (ch=0)
#pragma unroll
        for (int p = 0; p < 16; ++p) {
            int f = p * THREADS + tid;
            int r = f >> 5, q = f & 31;
            float4 a = P4[(size_t)sTgt[r] * 128 + ch * 32 + q];
            float4 b = Q4[(size_t)sSrc[r] * 128 + ch * 32 + q];
            float4 v;
            v.x = fmaxf(a.x + b.x, 0.f);
            v.y = fmaxf(a.y + b.y, 0.f);
            v.z = fmaxf(a.z + b.z, 0.f);
            v.w = fmaxf(a.w + b.w, 0.f);
            *(uint2*)(sH + r * HS2 + q * 4) = f4_to_h4(v);
        }
        for (int s = 0; s < 4; ++s) {
            __syncthreads();
            stage_wslab(sB, W2m + (size_t)(ch * 128 + s * 32) * D, D, tid);
            __syncthreads();
#pragma unroll
            for (int ks = 0; ks < 2; ++ks)
                mma_step(sH, HS2, s * 32 + ks * 16, sB, ks * 16, row0, n0, g, tig, accO);
        }
    }

    // permute accO through f32 area, then coalesced scatter
    __syncthreads();
#pragma unroll
    for (int s = 0; s < 2; ++s)
#pragma unroll
        for (int nt = 0; nt < 8; ++nt) {
            int r = row0 + s * 16 + g;
            int c = n0 + nt * 8 + tig * 2;
            *(float2*)&perm[r * PS + c] = make_float2(accO[s][nt][0], accO[s][nt][1]);
            *(float2*)&perm[(r + 8) * PS + c] = make_float2(accO[s][nt][2], accO[s][nt][3]);
        }
    __syncthreads();
#pragma unroll
    for (int i = 0; i < 8; ++i) {
        int r = ty * 8 + i;
        float4 v0 = *(float4*)&perm[r * PS + tx * 8];
        float4 v1 = *(float4*)&perm[r * PS + tx * 8 + 4];
        float* dst = g_agg + (size_t)sTgt[r] * D + tx * 8;
        asm volatile("red.global.add.v4.f32 [%0], {%1,%2,%3,%4};" ::
            "l"(dst), "f"(v0.x), "f"(v0.y), "f"(v0.z), "f"(v0.w) : "memory");
        asm volatile("red.global.add.v4.f32 [%0], {%1,%2,%3,%4};" ::
            "l"(dst + 4), "f"(v1.x), "f"(v1.y), "f"(v1.z), "f"(v1.w) : "memory");
    }
}

// ============ Update kernel: out = relu([x|agg]@W1u+b1u)@W2u+b2u ============
__global__ __launch_bounds__(THREADS, 1)
void update_kernel(const float* __restrict__ x,
                   const float* __restrict__ W1, const float* __restrict__ b1,
                   const float* __restrict__ W2, const float* __restrict__ b2,
                   float* __restrict__ outp) {
    extern __shared__ char smem[];
    __half* sA = (__half*)smem;                        // [128][SA2]
    __half* sH = (__half*)(smem + SZ_A2);              // [128][HS2]
    __half* sB = (__half*)(smem + SZ_A2 + SZ_H);       // [128][BS2]
    float* perm = (float*)smem;                        // epilogue overlays sA

    const int tid = threadIdx.x;
    const int lane = tid & 31;
    const int wid = tid >> 5;
    const int g = lane >> 2, tig = lane & 3;
    const int row0 = (wid >> 1) * 32, n0 = (wid & 1) * 64;
    const int ty = tid >> 4, tx = tid & 15;
    const int rowBase = blockIdx.x * TM;

    const float4* x4 = (const float4*)x;
    const float4* agg4 = (const float4*)g_agg;
#pragma unroll
    for (int p = 0; p < 32; ++p) {
        int f = p * THREADS + tid;
        int r = f >> 6, q = f & 63;
        int n = rowBase + r; if (n >= NN) n = 0;
        float4 v = (q < 32) ? x4[(size_t)n * 32 + q] : agg4[(size_t)n * 32 + (q - 32)];
        *(uint2*)(sA + r * SA2 + q * 4) = f4_to_h4(v);
    }

    float accO[2][8][4];
#pragma unroll
    for (int nt = 0; nt < 8; ++nt) {
        float2 bv = *(const float2*)&b2[n0 + nt * 8 + tig * 2];
#pragma unroll
        for (int s = 0; s < 2; ++s) {
            accO[s][nt][0] = bv.x; accO[s][nt][1] = bv.y;
            accO[s][nt][2] = bv.x; accO[s][nt][3] = bv.y;
        }
    }

    for (int ch = 0; ch < 4; ++ch) {
        float accH[2][8][4];
#pragma unroll
        for (int nt = 0; nt < 8; ++nt) {
            float2 bv = *(const float2*)&b1[ch * 128 + n0 + nt * 8 + tig * 2];
#pragma unroll
            for (int s = 0; s < 2; ++s) {
                accH[s][nt][0] = bv.x; accH[s][nt][1] = bv.y;
                accH[s][nt][2] = bv.x; accH[s][nt][3] = bv.y;
            }
        }
        for (int kb = 0; kb < 8; ++kb) {       // K1=256, 8 slabs
            __syncthreads();
            stage_wslab(sB, W1 + (size_t)(kb * 32) * DH + ch * 128, DH, tid);
            __syncthreads();
#pragma unroll
            for (int ks = 0; ks < 2; ++ks)
                mma_step(sA, SA2, kb * 32 + ks * 16, sB, ks * 16, row0, n0, g, tig, accH);
        }
        __syncthreads();
#pragma unroll
        for (int s = 0; s < 2; ++s)
#pragma unroll
            for (int nt = 0; nt < 8; ++nt) {
                int r = row0 + s * 16 + g;
                int c = n0 + nt * 8 + tig * 2;
                *(uint32_t*)(sH + r * HS2 + c) =
                    f2_to_h2(fmaxf(accH[s][nt][0], 0.f), fmaxf(accH[s][nt][1], 0.f));
                *(uint32_t*)(sH + (r + 8) * HS2 + c) =
                    f2_to_h2(fmaxf(accH[s][nt][2], 0.f), fmaxf(accH[s][nt][3], 0.f));
            }
        for (int kb = 0; kb < 4; ++kb) {
            __syncthreads();
            stage_wslab(sB, W2 + (size_t)(ch * 128 + kb * 32) * D, D, tid);
            __syncthreads();
#pragma unroll
            for (int ks = 0; ks < 2; ++ks)
                mma_step(sH, HS2, kb * 32 + ks * 16, sB, ks * 16, row0, n0, g, tig, accO);
        }
    }

    __syncthreads();
#pragma unroll
    for (int s = 0; s < 2; ++s)
#pragma unroll
        for (int nt = 0; nt < 8; ++nt) {
            int r = row0 + s * 16 + g;
            int c = n0 + nt * 8 + tig * 2;
            *(float2*)&perm[r * PS + c] = make_float2(accO[s][nt][0], accO[s][nt][1]);
            *(float2*)&perm[(r + 8) * PS + c] = make_float2(accO[s][nt][2], accO[s][nt][3]);
        }
    __syncthreads();
#pragma unroll
    for (int i = 0; i < 8; ++i) {
        int r = ty * 8 + i;
        int n = rowBase + r;
        if (n < NN) {
            float4 v0 = *(float4*)&perm[r * PS + tx * 8];
            float4 v1 = *(float4*)&perm[r * PS + tx * 8 + 4];
            *(float4*)&outp[(size_t)n * D + tx * 8] = v0;
            *(float4*)&outp[(size_t)n * D + tx * 8 + 4] = v1;
        }
    }
}

extern "C" void kernel_launch(void* const* d_in, const int* in_sizes, int n_in,
                              void* d_out, int out_size) {
    const float* x   = (const float*)d_in[0];
    const int* ei    = (const int*)d_in[2];   // int32 (JAX x64 disabled)
    const float* W1m = (const float*)d_in[3];
    const float* b1m = (const float*)d_in[4];
    const float* W2m = (const float*)d_in[5];
    const float* b2m = (const float*)d_in[6];
    const float* W1u = (const float*)d_in[7];
    const float* b1u = (const float*)d_in[8];
    const float* W2u = (const float*)d_in[9];
    const float* b2u = (const float*)d_in[10];

    cudaFuncSetAttribute(precompute_kernel,
                         cudaFuncAttributeMaxDynamicSharedMemorySize, PRE_SMEM);
    cudaFuncSetAttribute(edge_kernel,
                         cudaFuncAttributeMaxDynamicSharedMemorySize, EDGE_SMEM);
    cudaFuncSetAttribute(update_kernel,
                         cudaFuncAttributeMaxDynamicSharedMemorySize, UPD_SMEM);

    zero_agg_kernel<<<256, 256>>>();

    dim3 pgrid((NN + TM - 1) / TM, 2);
    precompute_kernel<<<pgrid, THREADS, PRE_SMEM>>>(x, W1m, b1m);

    edge_kernel<<<NE / TM, THREADS, EDGE_SMEM>>>(ei, W2m, b2m);

    update_kernel<<<(NN + TM - 1) / TM, THREADS, UPD_SMEM>>>(
        x, W1u, b1u, W2u, b2u, (float*)d_out);
}

// round 11
// speedup vs baseline: 9.0487x; 1.7305x over previous
#include <cuda_runtime.h>
#include <cuda_fp16.h>
#include <cstdint>

// Problem constants
#define NN      50000
#define NE      800000
#define D       128
#define DH      512
#define TM      128
#define THREADS 256
// half strides: word-stride mod 32 == 4 -> conflict-free frag loads
#define HS2     136      // [128][128+pad] chunk tiles
#define WS2     136      // weight chunk [n=128][k=128+pad]
#define SA2     264      // update A tile [128][256+pad]
#define WU2     264      // update W1 chunk [n=128][k=256+pad]
#define PS      132      // f32 permute stride

__device__ float  g_agg[NN * D];
__device__ __half g_Ph[NN * DH];        // x @ W1m_top + b1m  (fp16)
__device__ __half g_Qh[NN * DH];        // x @ W1m_bot        (fp16)
__device__ __half g_W1mh[DH * 256];     // [n=512][k=256]
__device__ __half g_W2mh[D * DH];       // [n=128][k=512]
__device__ __half g_W1uh[DH * 256];     // [n=512][k=256]
__device__ __half g_W2uh[D * DH];       // [n=128][k=512]

// smem byte layouts
#define SZ_H    (TM * HS2 * 2)          // 34816
#define SZ_W    (TM * WS2 * 2)          // 34816
#define SZ_A2   (TM * SA2 * 2)          // 67584
#define SZ_WU   (TM * WU2 * 2)          // 67584
#define SZ_PERM (TM * PS * 4)           // 67584
#define PRE_SMEM  (SZ_H + SZ_W)                     // 69632
#define EDGE_SMEM (SZ_H + SZ_W + 2 * TM * 4)        // 70656 (perm overlays sH+sW)
#define UPD_SMEM  (SZ_A2 + SZ_H + SZ_WU)            // 169984 (perm overlays sA)

__global__ void zero_agg_kernel() {
    float4 z = make_float4(0.f, 0.f, 0.f, 0.f);
    int total = NN * D / 4;
    for (int p = blockIdx.x * blockDim.x + threadIdx.x; p < total;
         p += gridDim.x * blockDim.x)
        ((float4*)g_agg)[p] = z;
}

// One-time: transpose all weights to fp16, n-major (k contiguous).
__global__ void prep_weights(const float* __restrict__ W1m, const float* __restrict__ W2m,
                             const float* __restrict__ W1u, const float* __restrict__ W2u) {
    const int total = (131072 + 65536 + 131072 + 65536) / 2;
    for (int t = blockIdx.x * blockDim.x + threadIdx.x; t < total;
         t += gridDim.x * blockDim.x) {
        int idx = t;
        if (idx < 65536) {                       // W1m [256][512] -> [512][256]
            int n = idx >> 7, kk = (idx & 127) * 2;
            *(half2*)&g_W1mh[n * 256 + kk] =
                __floats2half2_rn(W1m[kk * 512 + n], W1m[(kk + 1) * 512 + n]);
        } else if (idx < 98304) { idx -= 65536;  // W2m [512][128] -> [128][512]
            int n = idx >> 8, kk = (idx & 255) * 2;
            *(half2*)&g_W2mh[n * 512 + kk] =
                __floats2half2_rn(W2m[kk * 128 + n], W2m[(kk + 1) * 128 + n]);
        } else if (idx < 163840) { idx -= 98304; // W1u [256][512] -> [512][256]
            int n = idx >> 7, kk = (idx & 127) * 2;
            *(half2*)&g_W1uh[n * 256 + kk] =
                __floats2half2_rn(W1u[kk * 512 + n], W1u[(kk + 1) * 512 + n]);
        } else { idx -= 163840;                  // W2u [512][128] -> [128][512]
            int n = idx >> 8, kk = (idx & 255) * 2;
            *(half2*)&g_W2uh[n * 512 + kk] =
                __floats2half2_rn(W2u[kk * 128 + n], W2u[(kk + 1) * 128 + n]);
        }
    }
}

__device__ __forceinline__ int clamp_idx(int v) {
    v = v < 0 ? 0 : v;
    return v >= NN ? NN - 1 : v;
}
__device__ __forceinline__ uint2 f4_to_h4(float4 v) {
    half2 lo = __floats2half2_rn(v.x, v.y);
    half2 hi = __floats2half2_rn(v.z, v.w);
    uint2 r;
    r.x = *(uint32_t*)&lo;
    r.y = *(uint32_t*)&hi;
    return r;
}
__device__ __forceinline__ uint32_t f2_to_h2(float a, float b) {
    half2 h = __floats2half2_rn(a, b);
    return *(uint32_t*)&h;
}
__device__ __forceinline__ uint32_t hadd2_relu(uint32_t a, uint32_t b) {
    half2 r = __hmax2(__hadd2(*(half2*)&a, *(half2*)&b),
                      __float2half2_rn(0.f));
    return *(uint32_t*)&r;
}

__device__ __forceinline__ void mma_f16(float c[4],
                                        uint32_t a0, uint32_t a1, uint32_t a2, uint32_t a3,
                                        uint32_t b0, uint32_t b1) {
    asm volatile(
        "mma.sync.aligned.m16n8k16.row.col.f32.f16.f16.f32 "
        "{%0,%1,%2,%3}, {%4,%5,%6,%7}, {%8,%9}, {%0,%1,%2,%3};\n"
        : "+f"(c[0]), "+f"(c[1]), "+f"(c[2]), "+f"(c[3])
        : "r"(a0), "r"(a1), "r"(a2), "r"(a3), "r"(b0), "r"(b1));
}

// One k16 step: 2 m16 stripes x 8 n8 tiles (warp tile 32x64).
// sA: [row][k] halves stride LDA. sB: [n][k] halves stride LDB, k-offset kcol.
__device__ __forceinline__ void mma_step(const __half* __restrict__ sA, int LDA,
                                         const __half* __restrict__ sB, int LDB,
                                         int kcol, int row0, int n0, int g, int tig,
                                         float acc[2][8][4]) {
    uint32_t a[2][4];
#pragma unroll
    for (int s = 0; s < 2; ++s) {
        const __half* r0p = sA + (row0 + s * 16 + g) * LDA + kcol + 2 * tig;
        a[s][0] = *(const uint32_t*)r0p;
        a[s][1] = *(const uint32_t*)(r0p + 8 * LDA);
        a[s][2] = *(const uint32_t*)(r0p + 8);
        a[s][3] = *(const uint32_t*)(r0p + 8 * LDA + 8);
    }
    uint32_t b[8][2];
#pragma unroll
    for (int nt = 0; nt < 8; ++nt) {
        const __half* bb = sB + (n0 + nt * 8 + g) * LDB + kcol + 2 * tig;
        b[nt][0] = *(const uint32_t*)bb;
        b[nt][1] = *(const uint32_t*)(bb + 8);
    }
#pragma unroll
    for (int s = 0; s < 2; ++s)
#pragma unroll
        for (int nt = 0; nt < 8; ++nt)
            mma_f16(acc[s][nt], a[s][0], a[s][1], a[s][2], a[s][3],
                    b[nt][0], b[nt][1]);
}

// ============ Precompute: P = x@W1m[0:128] + b1m ; Q = x@W1m[128:256] (fp16 out) ============
__global__ __launch_bounds__(THREADS, 2)
void precompute_kernel(const float* __restrict__ x,
                       const float* __restrict__ b1m) {
    extern __shared__ char smem[];
    __half* sA = (__half*)smem;               // [128][HS2] x tile (k=128)
    __half* sW = (__half*)(smem + SZ_H);      // [128][WS2]

    const int tid = threadIdx.x;
    const int lane = tid & 31;
    const int wid = tid >> 5;
    const int g = lane >> 2, tig = lane & 3;
    const int row0 = (wid >> 1) * 32, n0 = (wid & 1) * 64;
    const int rowBase = blockIdx.x * TM;
    const int half_sel = blockIdx.y;

    const float4* x4 = (const float4*)x;
#pragma unroll
    for (int p = 0; p < 16; ++p) {
        int f = p * THREADS + tid;
        int r = f >> 5, q = f & 31;
        int n = rowBase + r; if (n >= NN) n = 0;
        *(uint2*)(sA + r * HS2 + q * 4) = f4_to_h4(x4[(size_t)n * 32 + q]);
    }

    __half* outArr = half_sel ? g_Qh : g_Ph;

    for (int ch = 0; ch < 4; ++ch) {
        __syncthreads();
        // stage W chunk [n=ch*128..+128][k=half_sel*128..+128]
#pragma unroll
        for (int p = 0; p < 8; ++p) {
            int f = p * THREADS + tid;
            int n_ = f >> 4, q = f & 15;
            uint4 w = *(const uint4*)&g_W1mh[(size_t)(ch * 128 + n_) * 256
                                             + half_sel * 128 + q * 8];
            *(uint4*)(sW + n_ * WS2 + q * 8) = w;
        }
        __syncthreads();

        float acc[2][8][4];
#pragma unroll
        for (int nt = 0; nt < 8; ++nt) {
            float2 bv = half_sel ? make_float2(0.f, 0.f)
                                 : *(const float2*)&b1m[ch * 128 + n0 + nt * 8 + tig * 2];
#pragma unroll
            for (int s = 0; s < 2; ++s) {
                acc[s][nt][0] = bv.x; acc[s][nt][1] = bv.y;
                acc[s][nt][2] = bv.x; acc[s][nt][3] = bv.y;
            }
        }
#pragma unroll
        for (int ks = 0; ks < 8; ++ks)
            mma_step(sA, HS2, sW, WS2, ks * 16, row0, n0, g, tig, acc);

#pragma unroll
        for (int s = 0; s < 2; ++s)
#pragma unroll
            for (int nt = 0; nt < 8; ++nt) {
                int r = row0 + s * 16 + g;
                int col = ch * 128 + n0 + nt * 8 + tig * 2;
                int n1 = rowBase + r, n2 = rowBase + r + 8;
                if (n1 < NN)
                    *(uint32_t*)&outArr[(size_t)n1 * DH + col] =
                        f2_to_h2(acc[s][nt][0], acc[s][nt][1]);
                if (n2 < NN)
                    *(uint32_t*)&outArr[(size_t)n2 * DH + col] =
                        f2_to_h2(acc[s][nt][2], acc[s][nt][3]);
            }
    }
}

// ============ Edge kernel: msg = relu(P[i]+Q[j]) @ W2m + b2m ; scatter ============
__global__ __launch_bounds__(THREADS, 2)
void edge_kernel(const int* __restrict__ edge_index,
                 const float* __restrict__ b2m) {
    extern __shared__ char smem[];
    __half* sH = (__half*)smem;               // [128][HS2]
    __half* sW = (__half*)(smem + SZ_H);      // [128][WS2]
    float* perm = (float*)smem;               // epilogue overlay
    int* sTgt = (int*)(smem + SZ_H + SZ_W);
    int* sSrc = sTgt + TM;

    const int tid = threadIdx.x;
    const int lane = tid & 31;
    const int wid = tid >> 5;
    const int g = lane >> 2, tig = lane & 3;
    const int row0 = (wid >> 1) * 32, n0 = (wid & 1) * 64;
    const int ty = tid >> 4, tx = tid & 15;
    const int rowBase = blockIdx.x * TM;

    if (tid < TM) {
        int e = rowBase + tid;
        sSrc[tid] = clamp_idx(edge_index[e]);        // source j
        sTgt[tid] = clamp_idx(edge_index[NE + e]);   // target i
    }

    float accO[2][8][4];
#pragma unroll
    for (int nt = 0; nt < 8; ++nt) {
        float2 bv = *(const float2*)&b2m[n0 + nt * 8 + tig * 2];
#pragma unroll
        for (int s = 0; s < 2; ++s) {
            accO[s][nt][0] = bv.x; accO[s][nt][1] = bv.y;
            accO[s][nt][2] = bv.x; accO[s][nt][3] = bv.y;
        }
    }

    for (int ch = 0; ch < 4; ++ch) {
        __syncthreads();   // prev mma done; idx visible (ch=0)
        // stage sH = relu(P[i]+Q[j]) fp16, uint4 = 8 cols
#pragma unroll
        for (int p = 0; p < 8; ++p) {
            int f = p * THREADS + tid;
            int r = f >> 4, q = f & 15;
            uint4 a = *(const uint4*)&g_Ph[(size_t)sTgt[r] * DH + ch * 128 + q * 8];
            uint4 b = *(const uint4*)&g_Qh[(size_t)sSrc[r] * DH + ch * 128 + q * 8];
            uint4 v;
            v.x = hadd2_relu(a.x, b.x);
            v.y = hadd2_relu(a.y, b.y);
            v.z = hadd2_relu(a.z, b.z);
            v.w = hadd2_relu(a.w, b.w);
            *(uint4*)(sH + r * HS2 + q * 8) = v;
        }
        // stage W2m chunk [n=128][k=ch*128..+128]
#pragma unroll
        for (int p = 0; p < 8; ++p) {
            int f = p * THREADS + tid;
            int n_ = f >> 4, q = f & 15;
            uint4 w = *(const uint4*)&g_W2mh[(size_t)n_ * DH + ch * 128 + q * 8];
            *(uint4*)(sW + n_ * WS2 + q * 8) = w;
        }
        __syncthreads();
#pragma unroll
        for (int ks = 0; ks < 8; ++ks)
            mma_step(sH, HS2, sW, WS2, ks * 16, row0, n0, g, tig, accO);
    }

    // permute accO -> f32 area, coalesced scatter
    __syncthreads();
#pragma unroll
    for (int s = 0; s < 2; ++s)
#pragma unroll
        for (int nt = 0; nt < 8; ++nt) {
            int r = row0 + s * 16 + g;
            int c = n0 + nt * 8 + tig * 2;
            *(float2*)&perm[r * PS + c] = make_float2(accO[s][nt][0], accO[s][nt][1]);
            *(float2*)&perm[(r + 8) * PS + c] = make_float2(accO[s][nt][2], accO[s][nt][3]);
        }
    __syncthreads();
#pragma unroll
    for (int i = 0; i < 8; ++i) {
        int r = ty * 8 + i;
        float4 v0 = *(float4*)&perm[r * PS + tx * 8];
        float4 v1 = *(float4*)&perm[r * PS + tx * 8 + 4];
        float* dst = g_agg + (size_t)sTgt[r] * D + tx * 8;
        asm volatile("red.global.add.v4.f32 [%0], {%1,%2,%3,%4};" ::
            "l"(dst), "f"(v0.x), "f"(v0.y), "f"(v0.z), "f"(v0.w) : "memory");
        asm volatile("red.global.add.v4.f32 [%0], {%1,%2,%3,%4};" ::
            "l"(dst + 4), "f"(v1.x), "f"(v1.y), "f"(v1.z), "f"(v1.w) : "memory");
    }
}

// ============ Update kernel: out = relu([x|agg]@W1u+b1u)@W2u+b2u ============
__global__ __launch_bounds__(THREADS, 1)
void update_kernel(const float* __restrict__ x,
                   const float* __restrict__ b1, const float* __restrict__ b2,
                   float* __restrict__ outp) {
    extern __shared__ char smem[];
    __half* sA = (__half*)smem;                        // [128][SA2]
    __half* sH = (__half*)(smem + SZ_A2);              // [128][HS2]
    __half* sW = (__half*)(smem + SZ_A2 + SZ_H);       // [128][WU2]
    float* perm = (float*)smem;                        // overlays sA

    const int tid = threadIdx.x;
    const int lane = tid & 31;
    const int wid = tid >> 5;
    const int g = lane >> 2, tig = lane & 3;
    const int row0 = (wid >> 1) * 32, n0 = (wid & 1) * 64;
    const int ty = tid >> 4, tx = tid & 15;
    const int rowBase = blockIdx.x * TM;

    const float4* x4 = (const float4*)x;
    const float4* agg4 = (const float4*)g_agg;
#pragma unroll
    for (int p = 0; p < 32; ++p) {
        int f = p * THREADS + tid;
        int r = f >> 6, q = f & 63;
        int n = rowBase + r; if (n >= NN) n = 0;
        float4 v = (q < 32) ? x4[(size_t)n * 32 + q] : agg4[(size_t)n * 32 + (q - 32)];
        *(uint2*)(sA + r * SA2 + q * 4) = f4_to_h4(v);
    }

    float accO[2][8][4];
#pragma unroll
    for (int nt = 0; nt < 8; ++nt) {
        float2 bv = *(const float2*)&b2[n0 + nt * 8 + tig * 2];
#pragma unroll
        for (int s = 0; s < 2; ++s) {
            accO[s][nt][0] = bv.x; accO[s][nt][1] = bv.y;
            accO[s][nt][2] = bv.x; accO[s][nt][3] = bv.y;
        }
    }

    for (int ch = 0; ch < 4; ++ch) {
        __syncthreads();
        // stage W1u chunk [n=ch*128..+128][k=0..256]
#pragma unroll
        for (int p = 0; p < 16; ++p) {
            int f = p * THREADS + tid;
            int n_ = f >> 5, q = f & 31;
            uint4 w = *(const uint4*)&g_W1uh[(size_t)(ch * 128 + n_) * 256 + q * 8];
            *(uint4*)(sW + n_ * WU2 + q * 8) = w;
        }
        __syncthreads();

        float accH[2][8][4];
#pragma unroll
        for (int nt = 0; nt < 8; ++nt) {
            float2 bv = *(const float2*)&b1[ch * 128 + n0 + nt * 8 + tig * 2];
#pragma unroll
            for (int s = 0; s < 2; ++s) {
                accH[s][nt][0] = bv.x; accH[s][nt][1] = bv.y;
                accH[s][nt][2] = bv.x; accH[s][nt][3] = bv.y;
            }
        }
#pragma unroll
        for (int ks = 0; ks < 16; ++ks)
            mma_step(sA, SA2, sW, WU2, ks * 16, row0, n0, g, tig, accH);

        __syncthreads();
        // write relu(accH) -> sH ; stage W2u chunk -> sW
#pragma unroll
        for (int s = 0; s < 2; ++s)
#pragma unroll
            for (int nt = 0; nt < 8; ++nt) {
                int r = row0 + s * 16 + g;
                int c = n0 + nt * 8 + tig * 2;
                *(uint32_t*)(sH + r * HS2 + c) =
                    f2_to_h2(fmaxf(accH[s][nt][0], 0.f), fmaxf(accH[s][nt][1], 0.f));
                *(uint32_t*)(sH + (r + 8) * HS2 + c) =
                    f2_to_h2(fmaxf(accH[s][nt][2], 0.f), fmaxf(accH[s][nt][3], 0.f));
            }
#pragma unroll
        for (int p = 0; p < 8; ++p) {
            int f = p * THREADS + tid;
            int n_ = f >> 4, q = f & 15;
            uint4 w = *(const uint4*)&g_W2uh[(size_t)n_ * DH + ch * 128 + q * 8];
            *(uint4*)(sW + n_ * WU2 + q * 8) = w;
        }
        __syncthreads();
#pragma unroll
        for (int ks = 0; ks < 8; ++ks)
            mma_step(sH, HS2, sW, WU2, ks * 16, row0, n0, g, tig, accO);
    }

    __syncthreads();
#pragma unroll
    for (int s = 0; s < 2; ++s)
#pragma unroll
        for (int nt = 0; nt < 8; ++nt) {
            int r = row0 + s * 16 + g;
            int c = n0 + nt * 8 + tig * 2;
            *(float2*)&perm[r * PS + c] = make_float2(accO[s][nt][0], accO[s][nt][1]);
            *(float2*)&perm[(r + 8) * PS + c] = make_float2(accO[s][nt][2], accO[s][nt][3]);
        }
    __syncthreads();
#pragma unroll
    for (int i = 0; i < 8; ++i) {
        int r = ty * 8 + i;
        int n = rowBase + r;
        if (n < NN) {
            float4 v0 = *(float4*)&perm[r * PS + tx * 8];
            float4 v1 = *(float4*)&perm[r * PS + tx * 8 + 4];
            *(float4*)&outp[(size_t)n * D + tx * 8] = v0;
            *(float4*)&outp[(size_t)n * D + tx * 8 + 4] = v1;
        }
    }
}

extern "C" void kernel_launch(void* const* d_in, const int* in_sizes, int n_in,
                              void* d_out, int out_size) {
    const float* x   = (const float*)d_in[0];
    const int* ei    = (const int*)d_in[2];   // int32 (JAX x64 disabled)
    const float* W1m = (const float*)d_in[3];
    const float* b1m = (const float*)d_in[4];
    const float* W2m = (const float*)d_in[5];
    const float* b2m = (const float*)d_in[6];
    const float* W1u = (const float*)d_in[7];
    const float* b1u = (const float*)d_in[8];
    const float* W2u = (const float*)d_in[9];
    const float* b2u = (const float*)d_in[10];

    cudaFuncSetAttribute(precompute_kernel,
                         cudaFuncAttributeMaxDynamicSharedMemorySize, PRE_SMEM);
    cudaFuncSetAttribute(edge_kernel,
                         cudaFuncAttributeMaxDynamicSharedMemorySize, EDGE_SMEM);
    cudaFuncSetAttribute(update_kernel,
                         cudaFuncAttributeMaxDynamicSharedMemorySize, UPD_SMEM);

    zero_agg_kernel<<<256, 256>>>();
    prep_weights<<<192, 256>>>(W1m, W2m, W1u, W2u);

    dim3 pgrid((NN + TM - 1) / TM, 2);
    precompute_kernel<<<pgrid, THREADS, PRE_SMEM>>>(x, b1m);

    edge_kernel<<<NE / TM, THREADS, EDGE_SMEM>>>(ei, b2m);

    update_kernel<<<(NN + TM - 1) / TM, THREADS, UPD_SMEM>>>(
        x, b1u, b2u, (float*)d_out);
}